// round 1
// baseline (speedup 1.0000x reference)
#include <cuda_runtime.h>
#include <math.h>

#define B_    2
#define C_IN  256
#define N_TOK 2304
#define H_    8
#define DH    64
#define NKV   2305   // n + 1 null token

// -------- scratch (device globals: no allocation allowed) --------
__device__ float g_invl2[B_ * N_TOK];                 // per-token 16/max(l2,eps)
__device__ float g_q[B_ * H_ * N_TOK * DH];           // q[b][h][i][d]  (also serves as k[j]=q[j-1])
__device__ float g_v[B_ * H_ * N_TOK * DH];           // v[b][h][i][d]
__device__ float g_o[B_ * H_ * DH * N_TOK];           // attn out, [b][h*64+d][i] layout for final GEMM

// ---------------- 1) per-token inverse L2 norm ----------------
__global__ __launch_bounds__(256) void norm_kernel(const float* __restrict__ fmap) {
    int idx = blockIdx.x * 256 + threadIdx.x;            // 0 .. B*N-1
    int bb = idx / N_TOK, i = idx - bb * N_TOK;
    const float* p = fmap + (size_t)bb * C_IN * N_TOK + i;
    float s = 0.f;
#pragma unroll 8
    for (int c = 0; c < C_IN; c++) { float x = p[(size_t)c * N_TOK]; s = fmaf(x, x, s); }
    g_invl2[idx] = 16.0f / fmaxf(sqrtf(s), 1e-12f);      // sqrt(256)=16
}

// ---------------- 2) fused qk/v projection GEMM ----------------
// C[i][o] = invl2[i] * sum_c (fmap[c][i]*gamma[c]) * W[o][c],  o in [0,1024): qk then v
__global__ __launch_bounds__(256) void proj_kernel(const float* __restrict__ fmap,
                                                   const float* __restrict__ gamma,
                                                   const float* __restrict__ w_qk,
                                                   const float* __restrict__ w_v) {
    __shared__ float As[16][64];   // [kk][i]
    __shared__ float Bs[16][64];   // [kk][o]
    const int i0 = blockIdx.x * 64;
    const int o0 = blockIdx.y * 64;
    const int bb = blockIdx.z;
    const bool isv = (o0 >= 512);
    const float* W = isv ? (w_v + (o0 - 512) * C_IN) : (w_qk + o0 * C_IN);
    const int h = (isv ? (o0 - 512) : o0) >> 6;

    const int tid = threadIdx.x;
    const int tr = tid >> 4, tc = tid & 15;
    const int ii = tid & 63, kq = tid >> 6;
    const int kkb = tid & 15, ob = tid >> 4;
    const float* Ab = fmap + (size_t)bb * C_IN * N_TOK + i0;

    float acc[4][4] = {};
    for (int k0 = 0; k0 < C_IN; k0 += 16) {
#pragma unroll
        for (int t = 0; t < 4; t++) {
            int kk = kq * 4 + t;
            As[kk][ii] = Ab[(size_t)(k0 + kk) * N_TOK + ii] * gamma[k0 + kk];
        }
#pragma unroll
        for (int t = 0; t < 4; t++) {
            int o = ob + 16 * t;
            Bs[kkb][o] = W[o * C_IN + k0 + kkb];
        }
        __syncthreads();
#pragma unroll
        for (int kk = 0; kk < 16; kk++) {
            float a[4], b[4];
#pragma unroll
            for (int x = 0; x < 4; x++) a[x] = As[kk][tr * 4 + x];
#pragma unroll
            for (int y = 0; y < 4; y++) b[y] = Bs[kk][tc * 4 + y];
#pragma unroll
            for (int x = 0; x < 4; x++)
#pragma unroll
                for (int y = 0; y < 4; y++) acc[x][y] = fmaf(a[x], b[y], acc[x][y]);
        }
        __syncthreads();
    }
    float* dst = isv ? g_v : g_q;
#pragma unroll
    for (int x = 0; x < 4; x++) {
        int i = i0 + tr * 4 + x;
        float sc = g_invl2[bb * N_TOK + i];
#pragma unroll
        for (int y = 0; y < 4; y++) {
            int d = tc * 4 + y;
            dst[((size_t)(bb * H_ + h) * N_TOK + i) * DH + d] = acc[x][y] * sc;
        }
    }
}

// ---------------- 3) flash attention (distance kernel) ----------------
// smem: q_s[64][65] | kp_s[64][65] (K tile, reused for P) | v_s[64][65] | q2[64] | k2[64]
#define AT_S 65
#define SMEM_ATTN ((3 * 64 * AT_S + 128) * 4)

__global__ __launch_bounds__(256) void attn_kernel(const float* __restrict__ nullkv) {
    extern __shared__ float sm[];
    float* q_s  = sm;
    float* k_s  = sm + 64 * AT_S;      // also holds P
    float* v_s  = sm + 2 * 64 * AT_S;
    float* q2_s = sm + 3 * 64 * AT_S;
    float* k2_s = q2_s + 64;

    const int tid = threadIdx.x;
    const int tr = tid >> 4, tc = tid & 15;
    const int i0 = blockIdx.x * 64;
    const int h  = blockIdx.y;
    const int bb = blockIdx.z;
    const float* qb = g_q + ((size_t)(bb * H_ + h) * N_TOK) * DH;
    const float* vb = g_v + ((size_t)(bb * H_ + h) * N_TOK) * DH;
    const float* nk = nullkv + h * DH;
    const float* nv = nullkv + H_ * DH + h * DH;

    // load Q tile + rowwise q^2
    {
        int row = tid >> 2, seg = tid & 3;
        const float* src = qb + (size_t)(i0 + row) * DH + seg * 16;
        float ss = 0.f;
#pragma unroll
        for (int t = 0; t < 16; t++) {
            float x = src[t];
            q_s[row * AT_S + seg * 16 + t] = x;
            ss = fmaf(x, x, ss);
        }
        ss += __shfl_xor_sync(0xffffffffu, ss, 1, 4);
        ss += __shfl_xor_sync(0xffffffffu, ss, 2, 4);
        if (seg == 0) q2_s[row] = ss;
    }

    float m_i[4], l_i[4], acc[4][4];
#pragma unroll
    for (int x = 0; x < 4; x++) {
        m_i[x] = -1e30f; l_i[x] = 0.f;
#pragma unroll
        for (int y = 0; y < 4; y++) acc[x][y] = 0.f;
    }

    for (int j0 = 0; j0 < NKV; j0 += 64) {
        __syncthreads();   // prior P@V done; q_s visible on first iter
        // load K/V tile (+ rowwise k^2).  k[j] = null (j==0) else q[j-1]
        {
            int row = tid >> 2, seg = tid & 3;
            int jg = j0 + row;
            float ss = 0.f;
#pragma unroll
            for (int t = 0; t < 16; t++) {
                int dd = seg * 16 + t;
                float kv, vv;
                if (jg == 0)        { kv = nk[dd];                          vv = nv[dd]; }
                else if (jg < NKV)  { kv = qb[(size_t)(jg - 1) * DH + dd];  vv = vb[(size_t)(jg - 1) * DH + dd]; }
                else                { kv = 0.f;                             vv = 0.f; }
                k_s[row * AT_S + dd] = kv;
                v_s[row * AT_S + dd] = vv;
                ss = fmaf(kv, kv, ss);
            }
            ss += __shfl_xor_sync(0xffffffffu, ss, 1, 4);
            ss += __shfl_xor_sync(0xffffffffu, ss, 2, 4);
            if (seg == 0) k2_s[row] = ss;
        }
        __syncthreads();

        // S = -sqrt(max(q2+k2-2 q.k, 0)) / 8, masked
        float s[4][4] = {};
#pragma unroll 8
        for (int d = 0; d < 64; d++) {
            float aq[4], bk[4];
#pragma unroll
            for (int x = 0; x < 4; x++) aq[x] = q_s[(tr * 4 + x) * AT_S + d];
#pragma unroll
            for (int y = 0; y < 4; y++) bk[y] = k_s[(tc * 4 + y) * AT_S + d];
#pragma unroll
            for (int x = 0; x < 4; x++)
#pragma unroll
                for (int y = 0; y < 4; y++) s[x][y] = fmaf(aq[x], bk[y], s[x][y]);
        }
        float q2r[4], k2c[4];
#pragma unroll
        for (int x = 0; x < 4; x++) q2r[x] = q2_s[tr * 4 + x];
#pragma unroll
        for (int y = 0; y < 4; y++) k2c[y] = k2_s[tc * 4 + y];
#pragma unroll
        for (int x = 0; x < 4; x++) {
            int ig = i0 + tr * 4 + x;
#pragma unroll
            for (int y = 0; y < 4; y++) {
                int jg = j0 + tc * 4 + y;
                float d2 = fmaxf(q2r[x] + k2c[y] - 2.f * s[x][y], 0.f);
                float sv = -sqrtf(d2) * 0.125f;
                if (jg == ig + 1) sv = -100.f;
                if (jg >= NKV)    sv = -1e30f;
                s[x][y] = sv;
            }
        }
        // online softmax update (row groups of 16 lanes)
        float alpha[4];
#pragma unroll
        for (int x = 0; x < 4; x++) {
            float mx = fmaxf(fmaxf(s[x][0], s[x][1]), fmaxf(s[x][2], s[x][3]));
            mx = fmaxf(mx, __shfl_xor_sync(0xffffffffu, mx, 8, 16));
            mx = fmaxf(mx, __shfl_xor_sync(0xffffffffu, mx, 4, 16));
            mx = fmaxf(mx, __shfl_xor_sync(0xffffffffu, mx, 2, 16));
            mx = fmaxf(mx, __shfl_xor_sync(0xffffffffu, mx, 1, 16));
            float mn = fmaxf(m_i[x], mx);
            alpha[x] = (m_i[x] < -1e29f) ? 0.f : __expf(m_i[x] - mn);
            float ps = 0.f;
#pragma unroll
            for (int y = 0; y < 4; y++) {
                float p = (s[x][y] > -1e29f) ? __expf(s[x][y] - mn) : 0.f;
                s[x][y] = p;          // s now holds P
                ps += p;
            }
            ps += __shfl_xor_sync(0xffffffffu, ps, 8, 16);
            ps += __shfl_xor_sync(0xffffffffu, ps, 4, 16);
            ps += __shfl_xor_sync(0xffffffffu, ps, 2, 16);
            ps += __shfl_xor_sync(0xffffffffu, ps, 1, 16);
            l_i[x] = l_i[x] * alpha[x] + ps;
            m_i[x] = mn;
#pragma unroll
            for (int y = 0; y < 4; y++) acc[x][y] *= alpha[x];
        }
        __syncthreads();   // everyone done reading k_s
#pragma unroll
        for (int x = 0; x < 4; x++)
#pragma unroll
            for (int y = 0; y < 4; y++) k_s[(tr * 4 + x) * AT_S + tc * 4 + y] = s[x][y];
        __syncthreads();

        // O += P @ V
#pragma unroll 8
        for (int j = 0; j < 64; j++) {
            float pa[4], vv[4];
#pragma unroll
            for (int x = 0; x < 4; x++) pa[x] = k_s[(tr * 4 + x) * AT_S + j];
#pragma unroll
            for (int y = 0; y < 4; y++) vv[y] = v_s[j * AT_S + tc * 4 + y];
#pragma unroll
            for (int x = 0; x < 4; x++)
#pragma unroll
                for (int y = 0; y < 4; y++) acc[x][y] = fmaf(pa[x], vv[y], acc[x][y]);
        }
    }
    // epilogue: divide by l, store as [b][h*64+d][i]
#pragma unroll
    for (int x = 0; x < 4; x++) {
        float inv = 1.f / l_i[x];
        int i = i0 + tr * 4 + x;
#pragma unroll
        for (int y = 0; y < 4; y++) {
            int d = tc * 4 + y;
            g_o[((size_t)bb * (H_ * DH) + h * DH + d) * N_TOK + i] = acc[x][y] * inv;
        }
    }
}

// ---------------- 4) output projection GEMM ----------------
// out[b][o][n] = sum_c w_out[o][c] * g_o[b][c][n],  o<256, c<512
__global__ __launch_bounds__(256) void outproj_kernel(const float* __restrict__ w_out,
                                                      float* __restrict__ out) {
    __shared__ float As[16][64];   // [kk][o]
    __shared__ float Bs[16][64];   // [kk][n]
    const int n0 = blockIdx.x * 64, o0 = blockIdx.y * 64, bb = blockIdx.z;
    const int tid = threadIdx.x, tr = tid >> 4, tc = tid & 15;
    const int kkb = tid & 15, ol0 = tid >> 4;
    const int nl = tid & 63, kq = tid >> 6;
    float acc[4][4] = {};
    for (int k0 = 0; k0 < 512; k0 += 16) {
#pragma unroll
        for (int t = 0; t < 4; t++) {
            int ol = ol0 + 16 * t;
            As[kkb][ol] = w_out[(o0 + ol) * 512 + k0 + kkb];
        }
#pragma unroll
        for (int t = 0; t < 4; t++) {
            int kk = kq * 4 + t;
            Bs[kk][nl] = g_o[((size_t)bb * 512 + k0 + kk) * N_TOK + n0 + nl];
        }
        __syncthreads();
#pragma unroll
        for (int kk = 0; kk < 16; kk++) {
            float a[4], b[4];
#pragma unroll
            for (int x = 0; x < 4; x++) a[x] = As[kk][tr * 4 + x];
#pragma unroll
            for (int y = 0; y < 4; y++) b[y] = Bs[kk][tc * 4 + y];
#pragma unroll
            for (int x = 0; x < 4; x++)
#pragma unroll
                for (int y = 0; y < 4; y++) acc[x][y] = fmaf(a[x], b[y], acc[x][y]);
        }
        __syncthreads();
    }
#pragma unroll
    for (int x = 0; x < 4; x++)
#pragma unroll
        for (int y = 0; y < 4; y++)
            out[(size_t)bb * 256 * N_TOK + (size_t)(o0 + tr * 4 + x) * N_TOK + n0 + tc * 4 + y] = acc[x][y];
}

// ---------------- launch ----------------
extern "C" void kernel_launch(void* const* d_in, const int* in_sizes, int n_in,
                              void* d_out, int out_size) {
    const float* fmap   = (const float*)d_in[0];
    const float* gamma  = (const float*)d_in[1];
    const float* w_qk   = (const float*)d_in[2];
    const float* w_v    = (const float*)d_in[3];
    const float* nullkv = (const float*)d_in[4];
    const float* w_out  = (const float*)d_in[5];
    float* out = (float*)d_out;

    cudaFuncSetAttribute(attn_kernel, cudaFuncAttributeMaxDynamicSharedMemorySize, SMEM_ATTN);

    norm_kernel<<<(B_ * N_TOK) / 256, 256>>>(fmap);
    proj_kernel<<<dim3(N_TOK / 64, 16, B_), 256>>>(fmap, gamma, w_qk, w_v);
    attn_kernel<<<dim3(N_TOK / 64, H_, B_), 256, SMEM_ATTN>>>(nullkv);
    outproj_kernel<<<dim3(N_TOK / 64, 4, B_), 256>>>(w_out, out);
}

// round 3
// speedup vs baseline: 2.1257x; 2.1257x over previous
#include <cuda_runtime.h>
#include <math.h>
#include <stdint.h>

#define B_    2
#define C_IN  256
#define N_TOK 2304
#define H_    8
#define DH    64
#define NKV   2305   // n + 1 null token

// -------- scratch (device globals: no allocation allowed) --------
__device__ float g_invl2[B_ * N_TOK];
__device__ float g_q[B_ * H_ * N_TOK * DH];           // q[b][h][i][d]; k[j]=q[j-1]
__device__ float g_v[B_ * H_ * N_TOK * DH];
__device__ float g_o[B_ * H_ * DH * N_TOK];           // [b][h*64+d][i]

// -------- tf32 helpers --------
__device__ __forceinline__ uint32_t tf32b(float x) {
    uint32_t r; asm("cvt.rna.tf32.f32 %0, %1;" : "=r"(r) : "f"(x)); return r;
}
__device__ __forceinline__ void mma8(float c[4], const uint32_t a[4], uint32_t b0, uint32_t b1) {
    asm("mma.sync.aligned.m16n8k8.row.col.f32.tf32.tf32.f32 "
        "{%0,%1,%2,%3},{%4,%5,%6,%7},{%8,%9},{%0,%1,%2,%3};"
        : "+f"(c[0]), "+f"(c[1]), "+f"(c[2]), "+f"(c[3])
        : "r"(a[0]), "r"(a[1]), "r"(a[2]), "r"(a[3]), "r"(b0), "r"(b1));
}

// ---------------- 1) per-token inverse L2 norm ----------------
__global__ __launch_bounds__(256) void norm_kernel(const float* __restrict__ fmap) {
    __shared__ float part[8][33];
    int i_loc = threadIdx.x & 31, cg = threadIdx.x >> 5;
    int idx = blockIdx.x * 32 + i_loc;
    int bb = idx / N_TOK, i = idx - bb * N_TOK;
    const float* p = fmap + (size_t)bb * C_IN * N_TOK + (size_t)cg * 32 * N_TOK + i;
    float s = 0.f;
#pragma unroll 8
    for (int c = 0; c < 32; c++) { float x = p[(size_t)c * N_TOK]; s = fmaf(x, x, s); }
    part[cg][i_loc] = s;
    __syncthreads();
    if (threadIdx.x < 32) {
        float t = 0.f;
#pragma unroll
        for (int g = 0; g < 8; g++) t += part[g][threadIdx.x];
        g_invl2[blockIdx.x * 32 + threadIdx.x] = 16.0f / fmaxf(sqrtf(t), 1e-12f);
    }
}

// ---------------- 2) fused qk/v projection GEMM ----------------
__global__ __launch_bounds__(256) void proj_kernel(const float* __restrict__ fmap,
                                                   const float* __restrict__ gamma,
                                                   const float* __restrict__ w_qk,
                                                   const float* __restrict__ w_v) {
    __shared__ float As[16][64];
    __shared__ float Bs[16][64];
    const int i0 = blockIdx.x * 64;
    const int o0 = blockIdx.y * 64;
    const int bb = blockIdx.z;
    const bool isv = (o0 >= 512);
    const float* W = isv ? (w_v + (o0 - 512) * C_IN) : (w_qk + o0 * C_IN);
    const int h = (isv ? (o0 - 512) : o0) >> 6;

    const int tid = threadIdx.x;
    const int tr = tid >> 4, tc = tid & 15;
    const int ii = tid & 63, kq = tid >> 6;
    const int kkb = tid & 15, ob = tid >> 4;
    const float* Ab = fmap + (size_t)bb * C_IN * N_TOK + i0;

    float acc[4][4] = {};
    for (int k0 = 0; k0 < C_IN; k0 += 16) {
#pragma unroll
        for (int t = 0; t < 4; t++) {
            int kk = kq * 4 + t;
            As[kk][ii] = Ab[(size_t)(k0 + kk) * N_TOK + ii] * gamma[k0 + kk];
        }
#pragma unroll
        for (int t = 0; t < 4; t++) {
            int o = ob + 16 * t;
            Bs[kkb][o] = W[o * C_IN + k0 + kkb];
        }
        __syncthreads();
#pragma unroll
        for (int kk = 0; kk < 16; kk++) {
            float a[4], b[4];
#pragma unroll
            for (int x = 0; x < 4; x++) a[x] = As[kk][tr * 4 + x];
#pragma unroll
            for (int y = 0; y < 4; y++) b[y] = Bs[kk][tc * 4 + y];
#pragma unroll
            for (int x = 0; x < 4; x++)
#pragma unroll
                for (int y = 0; y < 4; y++) acc[x][y] = fmaf(a[x], b[y], acc[x][y]);
        }
        __syncthreads();
    }
    float* dst = isv ? g_v : g_q;
#pragma unroll
    for (int x = 0; x < 4; x++) {
        int i = i0 + tr * 4 + x;
        float sc = g_invl2[bb * N_TOK + i];
#pragma unroll
        for (int y = 0; y < 4; y++) {
            int d = tc * 4 + y;
            dst[((size_t)(bb * H_ + h) * N_TOK + i) * DH + d] = acc[x][y] * sc;
        }
    }
}

// ---------------- 3) flash attention via tf32 mma ----------------
#define AKS 68
#define SM_ATTN ((2 * 64 * AKS + 64 + 4 * 16 * AKS) * 4)

__global__ __launch_bounds__(128, 4) void attn_mma_kernel(const float* __restrict__ nullkv) {
    extern __shared__ float sm[];
    float* k_s  = sm;                      // [64][AKS] tf32 bits of K [j][d]
    float* vT_s = sm + 64 * AKS;           // [64][AKS] tf32 bits of V^T [d][j]
    float* k2_s = sm + 2 * 64 * AKS;       // [64]
    float* p_s  = k2_s + 64;               // [4][16][AKS] per-warp P
    uint32_t* k_b  = (uint32_t*)k_s;
    uint32_t* vT_b = (uint32_t*)vT_s;
    uint32_t* p_b  = (uint32_t*)p_s;

    const int tid = threadIdx.x, lane = tid & 31, w = tid >> 5;
    const int i0 = blockIdx.x * 64, h = blockIdx.y, bb = blockIdx.z;
    const float* qb = g_q + ((size_t)(bb * H_ + h) * N_TOK) * DH;
    const float* vb = g_v + ((size_t)(bb * H_ + h) * N_TOK) * DH;
    const float* nk = nullkv + h * DH;
    const float* nv = nullkv + H_ * DH + h * DH;

    const int r0 = lane >> 2, cq = lane & 3;
    const int ig0 = i0 + w * 16 + r0, ig1 = ig0 + 8;

    // Q fragments (register-resident) + exact fp32 q^2 per row
    uint32_t aq[8][4];
    float q2r0 = 0.f, q2r1 = 0.f;
#pragma unroll
    for (int k = 0; k < 8; k++) {
        int c = k * 8 + cq;
        float x0 = qb[(size_t)ig0 * DH + c];
        float x1 = qb[(size_t)ig1 * DH + c];
        float x2 = qb[(size_t)ig0 * DH + c + 4];
        float x3 = qb[(size_t)ig1 * DH + c + 4];
        q2r0 = fmaf(x0, x0, fmaf(x2, x2, q2r0));
        q2r1 = fmaf(x1, x1, fmaf(x3, x3, q2r1));
        aq[k][0] = tf32b(x0); aq[k][1] = tf32b(x1);
        aq[k][2] = tf32b(x2); aq[k][3] = tf32b(x3);
    }
    q2r0 += __shfl_xor_sync(~0u, q2r0, 1); q2r0 += __shfl_xor_sync(~0u, q2r0, 2);
    q2r1 += __shfl_xor_sync(~0u, q2r1, 1); q2r1 += __shfl_xor_sync(~0u, q2r1, 2);

    float m0 = -1e30f, m1 = -1e30f, l0 = 0.f, l1 = 0.f;
    float o[8][4];
#pragma unroll
    for (int n = 0; n < 8; n++) { o[n][0] = o[n][1] = o[n][2] = o[n][3] = 0.f; }

    const int lrow = tid >> 1, lhalf = tid & 1;

    for (int j0 = 0; j0 < NKV; j0 += 64) {
        __syncthreads();
        // ---- load K / V^T tile + k^2 ----
        {
            int jg = j0 + lrow;
            float ss = 0.f;
            const float4* ks4; const float4* vs4;
            bool valid = (jg < NKV);
            if (jg == 0)      { ks4 = (const float4*)nk; vs4 = (const float4*)nv; }
            else if (valid)   { ks4 = (const float4*)(qb + (size_t)(jg - 1) * DH);
                                vs4 = (const float4*)(vb + (size_t)(jg - 1) * DH); }
            else              { ks4 = (const float4*)nk; vs4 = (const float4*)nv; } // dummy, zeroed below
#pragma unroll
            for (int t = 0; t < 8; t++) {
                float4 kv4 = ks4[lhalf * 8 + t];
                float4 vv4 = vs4[lhalf * 8 + t];
                if (!valid) { kv4 = make_float4(0.f,0.f,0.f,0.f); vv4 = kv4; }
                ss = fmaf(kv4.x,kv4.x,fmaf(kv4.y,kv4.y,fmaf(kv4.z,kv4.z,fmaf(kv4.w,kv4.w,ss))));
                int dd = lhalf * 32 + t * 4;
                k_b[lrow * AKS + dd + 0] = tf32b(kv4.x);
                k_b[lrow * AKS + dd + 1] = tf32b(kv4.y);
                k_b[lrow * AKS + dd + 2] = tf32b(kv4.z);
                k_b[lrow * AKS + dd + 3] = tf32b(kv4.w);
                vT_b[(dd + 0) * AKS + lrow] = tf32b(vv4.x);
                vT_b[(dd + 1) * AKS + lrow] = tf32b(vv4.y);
                vT_b[(dd + 2) * AKS + lrow] = tf32b(vv4.z);
                vT_b[(dd + 3) * AKS + lrow] = tf32b(vv4.w);
            }
            ss += __shfl_xor_sync(~0u, ss, 1);
            if (!lhalf) k2_s[lrow] = ss;
        }
        __syncthreads();

        // ---- S = Q K^T (tensor pipe) ----
        float sC[8][4];
#pragma unroll
        for (int n = 0; n < 8; n++) {
            sC[n][0] = sC[n][1] = sC[n][2] = sC[n][3] = 0.f;
            uint32_t base = (n * 8 + r0) * AKS + cq;
#pragma unroll
            for (int k = 0; k < 8; k++) {
                uint32_t b0 = k_b[base + k * 8];
                uint32_t b1 = k_b[base + k * 8 + 4];
                mma8(sC[n], aq[k], b0, b1);
            }
        }

        // ---- distances + masks + online softmax ----
        float rmax0 = -1e30f, rmax1 = -1e30f;
#pragma unroll
        for (int n = 0; n < 8; n++) {
            int jb = j0 + n * 8 + 2 * cq;
            float k2a = k2_s[n * 8 + 2 * cq];
            float k2b = k2_s[n * 8 + 2 * cq + 1];
            float d2, sv;
            d2 = fmaxf(q2r0 + k2a - 2.f * sC[n][0], 0.f); sv = -sqrtf(d2) * 0.125f;
            if (jb == ig0 + 1) sv = -100.f;  if (jb >= NKV) sv = -1e30f;
            sC[n][0] = sv; rmax0 = fmaxf(rmax0, sv);
            d2 = fmaxf(q2r0 + k2b - 2.f * sC[n][1], 0.f); sv = -sqrtf(d2) * 0.125f;
            if (jb + 1 == ig0 + 1) sv = -100.f;  if (jb + 1 >= NKV) sv = -1e30f;
            sC[n][1] = sv; rmax0 = fmaxf(rmax0, sv);
            d2 = fmaxf(q2r1 + k2a - 2.f * sC[n][2], 0.f); sv = -sqrtf(d2) * 0.125f;
            if (jb == ig1 + 1) sv = -100.f;  if (jb >= NKV) sv = -1e30f;
            sC[n][2] = sv; rmax1 = fmaxf(rmax1, sv);
            d2 = fmaxf(q2r1 + k2b - 2.f * sC[n][3], 0.f); sv = -sqrtf(d2) * 0.125f;
            if (jb + 1 == ig1 + 1) sv = -100.f;  if (jb + 1 >= NKV) sv = -1e30f;
            sC[n][3] = sv; rmax1 = fmaxf(rmax1, sv);
        }
        rmax0 = fmaxf(rmax0, __shfl_xor_sync(~0u, rmax0, 1));
        rmax0 = fmaxf(rmax0, __shfl_xor_sync(~0u, rmax0, 2));
        rmax1 = fmaxf(rmax1, __shfl_xor_sync(~0u, rmax1, 1));
        rmax1 = fmaxf(rmax1, __shfl_xor_sync(~0u, rmax1, 2));
        float mn0 = fmaxf(m0, rmax0), mn1 = fmaxf(m1, rmax1);
        float al0 = __expf(m0 - mn0), al1 = __expf(m1 - mn1);
        float ps0 = 0.f, ps1 = 0.f;
#pragma unroll
        for (int n = 0; n < 8; n++) {
            float p0 = __expf(sC[n][0] - mn0);
            float p1 = __expf(sC[n][1] - mn0);
            float p2 = __expf(sC[n][2] - mn1);
            float p3 = __expf(sC[n][3] - mn1);
            sC[n][0] = p0; sC[n][1] = p1; sC[n][2] = p2; sC[n][3] = p3;
            ps0 += p0 + p1; ps1 += p2 + p3;
            o[n][0] *= al0; o[n][1] *= al0; o[n][2] *= al1; o[n][3] *= al1;
        }
        ps0 += __shfl_xor_sync(~0u, ps0, 1); ps0 += __shfl_xor_sync(~0u, ps0, 2);
        ps1 += __shfl_xor_sync(~0u, ps1, 1); ps1 += __shfl_xor_sync(~0u, ps1, 2);
        l0 = l0 * al0 + ps0; l1 = l1 * al1 + ps1;
        m0 = mn0; m1 = mn1;

        // ---- stage P (per-warp), then O += P V ----
        uint32_t* pw = p_b + w * 16 * AKS;
#pragma unroll
        for (int n = 0; n < 8; n++) {
            int c = n * 8 + 2 * cq;
            pw[r0 * AKS + c]       = tf32b(sC[n][0]);
            pw[r0 * AKS + c + 1]   = tf32b(sC[n][1]);
            pw[(r0 + 8) * AKS + c]     = tf32b(sC[n][2]);
            pw[(r0 + 8) * AKS + c + 1] = tf32b(sC[n][3]);
        }
        __syncwarp();
#pragma unroll
        for (int k = 0; k < 8; k++) {
            uint32_t ap[4];
            ap[0] = pw[r0 * AKS + k * 8 + cq];
            ap[1] = pw[(r0 + 8) * AKS + k * 8 + cq];
            ap[2] = pw[r0 * AKS + k * 8 + cq + 4];
            ap[3] = pw[(r0 + 8) * AKS + k * 8 + cq + 4];
#pragma unroll
            for (int n = 0; n < 8; n++) {
                uint32_t b0 = vT_b[(n * 8 + r0) * AKS + k * 8 + cq];
                uint32_t b1 = vT_b[(n * 8 + r0) * AKS + k * 8 + cq + 4];
                mma8(o[n], ap, b0, b1);
            }
        }
    }

    // ---- epilogue: /l, store [b][h*64+d][i] ----
    float inv0 = 1.f / l0, inv1 = 1.f / l1;
    float* ob = g_o + ((size_t)bb * (H_ * DH) + h * DH) * N_TOK;
#pragma unroll
    for (int n = 0; n < 8; n++) {
        int d = n * 8 + 2 * cq;
        ob[(size_t)d * N_TOK + ig0]       = o[n][0] * inv0;
        ob[(size_t)(d + 1) * N_TOK + ig0] = o[n][1] * inv0;
        ob[(size_t)d * N_TOK + ig1]       = o[n][2] * inv1;
        ob[(size_t)(d + 1) * N_TOK + ig1] = o[n][3] * inv1;
    }
}

// ---------------- 4) output projection GEMM ----------------
__global__ __launch_bounds__(256) void outproj_kernel(const float* __restrict__ w_out,
                                                      float* __restrict__ out) {
    __shared__ float As[16][64];
    __shared__ float Bs[16][64];
    const int n0 = blockIdx.x * 64, o0 = blockIdx.y * 64, bb = blockIdx.z;
    const int tid = threadIdx.x, tr = tid >> 4, tc = tid & 15;
    const int kkb = tid & 15, ol0 = tid >> 4;
    const int nl = tid & 63, kq = tid >> 6;
    float acc[4][4] = {};
    for (int k0 = 0; k0 < 512; k0 += 16) {
#pragma unroll
        for (int t = 0; t < 4; t++) {
            int ol = ol0 + 16 * t;
            As[kkb][ol] = w_out[(o0 + ol) * 512 + k0 + kkb];
        }
#pragma unroll
        for (int t = 0; t < 4; t++) {
            int kk = kq * 4 + t;
            Bs[kk][nl] = g_o[((size_t)bb * 512 + k0 + kk) * N_TOK + n0 + nl];
        }
        __syncthreads();
#pragma unroll
        for (int kk = 0; kk < 16; kk++) {
            float a[4], b[4];
#pragma unroll
            for (int x = 0; x < 4; x++) a[x] = As[kk][tr * 4 + x];
#pragma unroll
            for (int y = 0; y < 4; y++) b[y] = Bs[kk][tc * 4 + y];
#pragma unroll
            for (int x = 0; x < 4; x++)
#pragma unroll
                for (int y = 0; y < 4; y++) acc[x][y] = fmaf(a[x], b[y], acc[x][y]);
        }
        __syncthreads();
    }
#pragma unroll
    for (int x = 0; x < 4; x++)
#pragma unroll
        for (int y = 0; y < 4; y++)
            out[(size_t)bb * 256 * N_TOK + (size_t)(o0 + tr * 4 + x) * N_TOK + n0 + tc * 4 + y] = acc[x][y];
}

// ---------------- launch ----------------
extern "C" void kernel_launch(void* const* d_in, const int* in_sizes, int n_in,
                              void* d_out, int out_size) {
    const float* fmap   = (const float*)d_in[0];
    const float* gamma  = (const float*)d_in[1];
    const float* w_qk   = (const float*)d_in[2];
    const float* w_v    = (const float*)d_in[3];
    const float* nullkv = (const float*)d_in[4];
    const float* w_out  = (const float*)d_in[5];
    float* out = (float*)d_out;

    cudaFuncSetAttribute(attn_mma_kernel, cudaFuncAttributeMaxDynamicSharedMemorySize, SM_ATTN);

    norm_kernel<<<(B_ * N_TOK) / 32, 256>>>(fmap);
    proj_kernel<<<dim3(N_TOK / 64, 16, B_), 256>>>(fmap, gamma, w_qk, w_v);
    attn_mma_kernel<<<dim3(N_TOK / 64, H_, B_), 128, SM_ATTN>>>(nullkv);
    outproj_kernel<<<dim3(N_TOK / 64, 4, B_), 256>>>(w_out, out);
}

// round 4
// speedup vs baseline: 2.9576x; 1.3914x over previous
#include <cuda_runtime.h>
#include <math.h>
#include <stdint.h>

#define B_    2
#define C_IN  256
#define N_TOK 2304
#define H_    8
#define DH    64
#define NKV   2305    // n + 1 null token
#define NKV_PAD 2368  // 37*64, for padded k2 tiles

// -------- scratch (device globals) --------
__device__ float g_invl2[B_ * N_TOK];
__device__ float g_k [B_ * H_ * NKV * DH];   // row 0 = null k, row j = q[j-1]; tf32-rounded
__device__ float g_v2[B_ * H_ * NKV * DH];   // row 0 = null v, row j = v[j-1]; tf32-rounded
__device__ float g_k2[B_ * H_ * NKV_PAD];    // per-row |k|^2 (of rounded values)
__device__ float g_o [B_ * H_ * DH * N_TOK]; // attn out [b][h*64+d][i]

// -------- helpers --------
__device__ __forceinline__ uint32_t tf32b(float x) {
    uint32_t r; asm("cvt.rna.tf32.f32 %0, %1;" : "=r"(r) : "f"(x)); return r;
}
__device__ __forceinline__ void mma8(float c[4], const uint32_t a[4], uint32_t b0, uint32_t b1) {
    asm("mma.sync.aligned.m16n8k8.row.col.f32.tf32.tf32.f32 "
        "{%0,%1,%2,%3},{%4,%5,%6,%7},{%8,%9},{%0,%1,%2,%3};"
        : "+f"(c[0]), "+f"(c[1]), "+f"(c[2]), "+f"(c[3])
        : "r"(a[0]), "r"(a[1]), "r"(a[2]), "r"(a[3]), "r"(b0), "r"(b1));
}
__device__ __forceinline__ void cpasync16(uint32_t dst, const float* src) {
    asm volatile("cp.async.ca.shared.global [%0], [%1], 16;" :: "r"(dst), "l"(src));
}
__device__ __forceinline__ void cpcommit() { asm volatile("cp.async.commit_group;"); }

// ---------------- 0) null token rows ----------------
__global__ void null_init(const float* __restrict__ nullkv) {
    int tid = threadIdx.x;  // 128
#pragma unroll
    for (int t = 0; t < 8; t++) {
        int idx = tid + 128 * t;           // 0..1023
        int bh = idx >> 6, d = idx & 63, h = bh & 7;
        g_k [(size_t)bh * NKV * DH + d] = __uint_as_float(tf32b(nullkv[h * DH + d]));
        g_v2[(size_t)bh * NKV * DH + d] = __uint_as_float(tf32b(nullkv[H_ * DH + h * DH + d]));
    }
    if (tid < 16) {
        int h = tid & 7; float s = 0.f;
#pragma unroll 8
        for (int d = 0; d < 64; d++) {
            float x = __uint_as_float(tf32b(nullkv[h * DH + d]));
            s = fmaf(x, x, s);
        }
        g_k2[(size_t)tid * NKV_PAD] = s;
    }
}

// ---------------- 1) per-token inverse L2 norm ----------------
__global__ __launch_bounds__(256) void norm_kernel(const float* __restrict__ fmap) {
    __shared__ float part[8][33];
    int i_loc = threadIdx.x & 31, cg = threadIdx.x >> 5;
    int idx = blockIdx.x * 32 + i_loc;
    int bb = idx / N_TOK, i = idx - bb * N_TOK;
    const float* p = fmap + (size_t)bb * C_IN * N_TOK + (size_t)cg * 32 * N_TOK + i;
    float s = 0.f;
#pragma unroll 8
    for (int c = 0; c < 32; c++) { float x = p[(size_t)c * N_TOK]; s = fmaf(x, x, s); }
    part[cg][i_loc] = s;
    __syncthreads();
    if (threadIdx.x < 32) {
        float t = 0.f;
#pragma unroll
        for (int g = 0; g < 8; g++) t += part[g][threadIdx.x];
        g_invl2[blockIdx.x * 32 + threadIdx.x] = 16.0f / fmaxf(sqrtf(t), 1e-12f);
    }
}

// ---------------- 2) fused qk/v projection GEMM ----------------
// writes tf32-rounded q/v into g_k/g_v2 at row i+1; k2 for qk heads
__global__ __launch_bounds__(256) void proj_kernel(const float* __restrict__ fmap,
                                                   const float* __restrict__ gamma,
                                                   const float* __restrict__ w_qk,
                                                   const float* __restrict__ w_v) {
    __shared__ float As[16][64];
    __shared__ float Bs[16][64];
    const int i0 = blockIdx.x * 64;
    const int o0 = blockIdx.y * 64;
    const int bb = blockIdx.z;
    const bool isv = (o0 >= 512);
    const float* W = isv ? (w_v + (o0 - 512) * C_IN) : (w_qk + o0 * C_IN);
    const int h = (isv ? (o0 - 512) : o0) >> 6;
    const int bh = bb * H_ + h;

    const int tid = threadIdx.x;
    const int tr = tid >> 4, tc = tid & 15;
    const int ii = tid & 63, kq = tid >> 6;
    const int kkb = tid & 15, ob = tid >> 4;
    const float* Ab = fmap + (size_t)bb * C_IN * N_TOK + i0;

    float acc[4][4] = {};
    for (int k0 = 0; k0 < C_IN; k0 += 16) {
#pragma unroll
        for (int t = 0; t < 4; t++) {
            int kk = kq * 4 + t;
            As[kk][ii] = Ab[(size_t)(k0 + kk) * N_TOK + ii] * gamma[k0 + kk];
        }
#pragma unroll
        for (int t = 0; t < 4; t++) {
            int o = ob + 16 * t;
            Bs[kkb][o] = W[o * C_IN + k0 + kkb];
        }
        __syncthreads();
#pragma unroll
        for (int kk = 0; kk < 16; kk++) {
            float a[4], b[4];
#pragma unroll
            for (int x = 0; x < 4; x++) a[x] = As[kk][tr * 4 + x];
#pragma unroll
            for (int y = 0; y < 4; y++) b[y] = Bs[kk][tc * 4 + y];
#pragma unroll
            for (int x = 0; x < 4; x++)
#pragma unroll
                for (int y = 0; y < 4; y++) acc[x][y] = fmaf(a[x], b[y], acc[x][y]);
        }
        __syncthreads();
    }
    float* dst = isv ? g_v2 : g_k;
#pragma unroll
    for (int x = 0; x < 4; x++) {
        int i = i0 + tr * 4 + x;
        float sc = g_invl2[bb * N_TOK + i];
        float rs = 0.f;
#pragma unroll
        for (int y = 0; y < 4; y++) {
            int d = tc * 4 + y;
            float rv = __uint_as_float(tf32b(acc[x][y] * sc));
            dst[((size_t)bh * NKV + i + 1) * DH + d] = rv;
            rs = fmaf(rv, rv, rs);
        }
        if (!isv) {
            rs += __shfl_xor_sync(0xffffffffu, rs, 1);
            rs += __shfl_xor_sync(0xffffffffu, rs, 2);
            rs += __shfl_xor_sync(0xffffffffu, rs, 4);
            rs += __shfl_xor_sync(0xffffffffu, rs, 8);
            if (tc == 0) g_k2[(size_t)bh * NKV_PAD + i + 1] = rs;
        }
    }
}

// ---------------- 3) flash attention, tf32 mma, cp.async pipelined ----------------
#define KST 68   // K smem row stride (bank = 4*r0+cq : conflict-free)
#define VST 72   // V smem row stride (bank = 8*cq+r0 : conflict-free)
#define PST 68
#define SM_K0 0
#define SM_V0 (2 * 64 * KST)             // 8704
#define SM_K2 (SM_V0 + 2 * 64 * VST)     // 17920
#define SM_P  (SM_K2 + 128)              // 18048
#define SM_TOT ((SM_P + 8 * 16 * PST) * 4)   // 107008 B

__global__ __launch_bounds__(256, 2) void attn_mma_kernel() {
    extern __shared__ float sm[];
    const int tid = threadIdx.x, lane = tid & 31, w = tid >> 5;
    const int i0 = blockIdx.x * 128, h = blockIdx.y, bb = blockIdx.z;
    const int bh = bb * H_ + h;
    const float* kg  = g_k  + (size_t)bh * NKV * DH;
    const float* vg  = g_v2 + (size_t)bh * NKV * DH;
    const float* k2g = g_k2 + (size_t)bh * NKV_PAD;
    const float* qb  = kg + DH;          // q[i] = k[i+1]

    uint32_t smu = (uint32_t)__cvta_generic_to_shared(sm);

    const int r0 = lane >> 2, cq = lane & 3;
    const int ig0 = i0 + w * 16 + r0, ig1 = ig0 + 8;

    // Q fragments (already tf32-rounded in gmem)
    uint32_t aq[8][4];
#pragma unroll
    for (int k = 0; k < 8; k++) {
        int c = k * 8 + cq;
        aq[k][0] = __float_as_uint(qb[(size_t)ig0 * DH + c]);
        aq[k][1] = __float_as_uint(qb[(size_t)ig1 * DH + c]);
        aq[k][2] = __float_as_uint(qb[(size_t)ig0 * DH + c + 4]);
        aq[k][3] = __float_as_uint(qb[(size_t)ig1 * DH + c + 4]);
    }
    const float q2r0 = k2g[ig0 + 1], q2r1 = k2g[ig1 + 1];

    float m0 = -1e30f, m1 = -1e30f, l0 = 0.f, l1 = 0.f;
    float o[8][4];
#pragma unroll
    for (int n = 0; n < 8; n++) { o[n][0] = o[n][1] = o[n][2] = o[n][3] = 0.f; }

    // tile loader: K/V rows j0..j0+63 + k2 (clamped; garbage masked later)
    auto load_tile = [&](int buf, int j0) {
#pragma unroll
        for (int t = 0; t < 4; t++) {
            int c = tid + 256 * t;               // 0..1023
            int row = c >> 4, seg = (c & 15) * 4;
            int jg = j0 + row; if (jg > NKV - 1) jg = NKV - 1;
            cpasync16(smu + (uint32_t)(SM_K0 + buf * 64 * KST + row * KST + seg) * 4,
                      kg + (size_t)jg * DH + seg);
            cpasync16(smu + (uint32_t)(SM_V0 + buf * 64 * VST + row * VST + seg) * 4,
                      vg + (size_t)jg * DH + seg);
        }
        if (tid < 16)
            cpasync16(smu + (uint32_t)(SM_K2 + buf * 64 + tid * 4) * 4, k2g + j0 + tid * 4);
    };

    load_tile(0, 0);
    cpcommit();

    const int NT = (NKV + 63) / 64;   // 37
    for (int t = 0; t < NT; t++) {
        const int j0 = t * 64, buf = t & 1;
        if (t + 1 < NT) {
            if (t >= 1) __syncthreads();           // buffer (t+1)&1 free
            load_tile(buf ^ 1, j0 + 64);
            cpcommit();
            asm volatile("cp.async.wait_group 1;");
        } else {
            asm volatile("cp.async.wait_group 0;");
        }
        __syncthreads();

        const uint32_t* ksb = (const uint32_t*)(sm + SM_K0 + buf * 64 * KST);
        const uint32_t* vsb = (const uint32_t*)(sm + SM_V0 + buf * 64 * VST);
        const float*    k2s = sm + SM_K2 + buf * 64;
        uint32_t*       pwu = (uint32_t*)(sm + SM_P) + w * 16 * PST;

        // ---- S = Q K^T ----
        float sC[8][4];
#pragma unroll
        for (int n = 0; n < 8; n++) {
            sC[n][0] = sC[n][1] = sC[n][2] = sC[n][3] = 0.f;
            int base = (n * 8 + r0) * KST + cq;
#pragma unroll
            for (int k = 0; k < 8; k++)
                mma8(sC[n], aq[k], ksb[base + k * 8], ksb[base + k * 8 + 4]);
        }

        // ---- distance + mask + online softmax ----
        float rmax0 = -1e30f, rmax1 = -1e30f;
#pragma unroll
        for (int n = 0; n < 8; n++) {
            int jb = j0 + n * 8 + 2 * cq;
            float k2a = k2s[n * 8 + 2 * cq];
            float k2b = k2s[n * 8 + 2 * cq + 1];
            float d2, sv;
            d2 = fmaxf(q2r0 + k2a - 2.f * sC[n][0], 0.f); sv = -sqrtf(d2) * 0.125f;
            if (jb == ig0 + 1) sv = -100.f;  if (jb >= NKV) sv = -1e30f;
            sC[n][0] = sv; rmax0 = fmaxf(rmax0, sv);
            d2 = fmaxf(q2r0 + k2b - 2.f * sC[n][1], 0.f); sv = -sqrtf(d2) * 0.125f;
            if (jb + 1 == ig0 + 1) sv = -100.f;  if (jb + 1 >= NKV) sv = -1e30f;
            sC[n][1] = sv; rmax0 = fmaxf(rmax0, sv);
            d2 = fmaxf(q2r1 + k2a - 2.f * sC[n][2], 0.f); sv = -sqrtf(d2) * 0.125f;
            if (jb == ig1 + 1) sv = -100.f;  if (jb >= NKV) sv = -1e30f;
            sC[n][2] = sv; rmax1 = fmaxf(rmax1, sv);
            d2 = fmaxf(q2r1 + k2b - 2.f * sC[n][3], 0.f); sv = -sqrtf(d2) * 0.125f;
            if (jb + 1 == ig1 + 1) sv = -100.f;  if (jb + 1 >= NKV) sv = -1e30f;
            sC[n][3] = sv; rmax1 = fmaxf(rmax1, sv);
        }
        rmax0 = fmaxf(rmax0, __shfl_xor_sync(~0u, rmax0, 1));
        rmax0 = fmaxf(rmax0, __shfl_xor_sync(~0u, rmax0, 2));
        rmax1 = fmaxf(rmax1, __shfl_xor_sync(~0u, rmax1, 1));
        rmax1 = fmaxf(rmax1, __shfl_xor_sync(~0u, rmax1, 2));
        float mn0 = fmaxf(m0, rmax0), mn1 = fmaxf(m1, rmax1);
        float al0 = __expf(m0 - mn0), al1 = __expf(m1 - mn1);
        float ps0 = 0.f, ps1 = 0.f;
#pragma unroll
        for (int n = 0; n < 8; n++) {
            float p0 = __expf(sC[n][0] - mn0);
            float p1 = __expf(sC[n][1] - mn0);
            float p2 = __expf(sC[n][2] - mn1);
            float p3 = __expf(sC[n][3] - mn1);
            sC[n][0] = p0; sC[n][1] = p1; sC[n][2] = p2; sC[n][3] = p3;
            ps0 += p0 + p1; ps1 += p2 + p3;
            o[n][0] *= al0; o[n][1] *= al0; o[n][2] *= al1; o[n][3] *= al1;
        }
        ps0 += __shfl_xor_sync(~0u, ps0, 1); ps0 += __shfl_xor_sync(~0u, ps0, 2);
        ps1 += __shfl_xor_sync(~0u, ps1, 1); ps1 += __shfl_xor_sync(~0u, ps1, 2);
        l0 = l0 * al0 + ps0; l1 = l1 * al1 + ps1;
        m0 = mn0; m1 = mn1;

        // ---- stage P (per-warp), O += P V ----
#pragma unroll
        for (int n = 0; n < 8; n++) {
            int c = n * 8 + 2 * cq;
            pwu[r0 * PST + c]           = tf32b(sC[n][0]);
            pwu[r0 * PST + c + 1]       = tf32b(sC[n][1]);
            pwu[(r0 + 8) * PST + c]     = tf32b(sC[n][2]);
            pwu[(r0 + 8) * PST + c + 1] = tf32b(sC[n][3]);
        }
        __syncwarp();
#pragma unroll
        for (int k = 0; k < 8; k++) {
            uint32_t ap[4];
            ap[0] = pwu[r0 * PST + k * 8 + cq];
            ap[1] = pwu[(r0 + 8) * PST + k * 8 + cq];
            ap[2] = pwu[r0 * PST + k * 8 + cq + 4];
            ap[3] = pwu[(r0 + 8) * PST + k * 8 + cq + 4];
#pragma unroll
            for (int n = 0; n < 8; n++) {
                uint32_t b0 = vsb[(k * 8 + cq) * VST + n * 8 + r0];
                uint32_t b1 = vsb[(k * 8 + cq + 4) * VST + n * 8 + r0];
                mma8(o[n], ap, b0, b1);
            }
        }
    }

    // ---- epilogue ----
    float inv0 = 1.f / l0, inv1 = 1.f / l1;
    float* ob = g_o + ((size_t)bb * (H_ * DH) + h * DH) * N_TOK;
#pragma unroll
    for (int n = 0; n < 8; n++) {
        int d = n * 8 + 2 * cq;
        ob[(size_t)d * N_TOK + ig0]       = o[n][0] * inv0;
        ob[(size_t)(d + 1) * N_TOK + ig0] = o[n][1] * inv0;
        ob[(size_t)d * N_TOK + ig1]       = o[n][2] * inv1;
        ob[(size_t)(d + 1) * N_TOK + ig1] = o[n][3] * inv1;
    }
}

// ---------------- 4) output projection GEMM (32x64 tiles, 576 blocks) ----------------
__global__ __launch_bounds__(128) void outproj_kernel(const float* __restrict__ w_out,
                                                      float* __restrict__ out) {
    __shared__ float As[16][32];   // [kk][o]
    __shared__ float Bs[16][64];   // [kk][n]
    const int n0 = blockIdx.x * 64, o0 = blockIdx.y * 32, bb = blockIdx.z;
    const int tid = threadIdx.x, tr = tid >> 4, tc = tid & 15;
    const int kkA = tid & 15, oA = tid >> 4;        // coalesced w_out loads
    const int nB = tid & 63, kB = tid >> 6;
    float acc[4][4] = {};
    for (int k0 = 0; k0 < 512; k0 += 16) {
#pragma unroll
        for (int t = 0; t < 4; t++) {
            int o = oA + 8 * t;
            As[kkA][o] = w_out[(o0 + o) * 512 + k0 + kkA];
        }
#pragma unroll
        for (int t = 0; t < 8; t++) {
            int kk = kB + 2 * t;
            Bs[kk][nB] = g_o[((size_t)bb * 512 + k0 + kk) * N_TOK + n0 + nB];
        }
        __syncthreads();
#pragma unroll
        for (int kk = 0; kk < 16; kk++) {
            float a[4], b[4];
#pragma unroll
            for (int x = 0; x < 4; x++) a[x] = As[kk][tr * 4 + x];
#pragma unroll
            for (int y = 0; y < 4; y++) b[y] = Bs[kk][tc * 4 + y];
#pragma unroll
            for (int x = 0; x < 4; x++)
#pragma unroll
                for (int y = 0; y < 4; y++) acc[x][y] = fmaf(a[x], b[y], acc[x][y]);
        }
        __syncthreads();
    }
#pragma unroll
    for (int x = 0; x < 4; x++)
#pragma unroll
        for (int y = 0; y < 4; y++)
            out[(size_t)bb * 256 * N_TOK + (size_t)(o0 + tr * 4 + x) * N_TOK + n0 + tc * 4 + y] = acc[x][y];
}

// ---------------- launch ----------------
extern "C" void kernel_launch(void* const* d_in, const int* in_sizes, int n_in,
                              void* d_out, int out_size) {
    const float* fmap   = (const float*)d_in[0];
    const float* gamma  = (const float*)d_in[1];
    const float* w_qk   = (const float*)d_in[2];
    const float* w_v    = (const float*)d_in[3];
    const float* nullkv = (const float*)d_in[4];
    const float* w_out  = (const float*)d_in[5];
    float* out = (float*)d_out;

    cudaFuncSetAttribute(attn_mma_kernel, cudaFuncAttributeMaxDynamicSharedMemorySize, SM_TOT);

    null_init<<<1, 128>>>(nullkv);
    norm_kernel<<<(B_ * N_TOK) / 32, 256>>>(fmap);
    proj_kernel<<<dim3(N_TOK / 64, 16, B_), 256>>>(fmap, gamma, w_qk, w_v);
    attn_mma_kernel<<<dim3(N_TOK / 128, H_, B_), 256, SM_TOT>>>();
    outproj_kernel<<<dim3(N_TOK / 64, 8, B_), 128>>>(w_out, out);
}